// round 2
// baseline (speedup 1.0000x reference)
#include <cuda_runtime.h>
#include <float.h>
#include <math.h>

// Problem constants
#define BB 4
#define NN 1024
#define DQ 256
#define HH 8
#define DD 32
#define MM (BB * NN)          // 4096 rows
#define KK 256                 // inner dim for all projections
#define QSCALE 0.17677669529663687f  // 32^-0.5

// -------- scratch (no cudaMalloc allowed) --------
__device__ float g_q[BB * HH * NN * DD];     // [bh, n, d], pre-scaled
__device__ float g_k[BB * HH * NN * DD];
__device__ float g_v[BB * HH * NN * DD];
__device__ float g_gate[MM * DQ];            // sigmoid(x Wg^T + bg)
__device__ float g_t[MM * DQ];               // gated attention output

// ---------------- tiled GEMM: C[m,e] = sum_k A[m,k] * W[e,k] ----------------
// BM=64, BE=64, BK=32, 256 threads, 4x4 microtile per thread.
#define BM 64
#define BE 64
#define BKc 32

// MODE: 0=Q proj, 1=KV proj, 2=Gate proj, 3=Output proj (A is read from g_t)
template <int MODE>
__global__ __launch_bounds__(256, 4) void gemm_kernel(
    const float* __restrict__ A_in, const float* __restrict__ W,
    const float* __restrict__ bvec, float* __restrict__ C)
{
    __shared__ float As[BKc][BM];
    __shared__ float Ws[BKc][BE];

    const float* A = (MODE == 3) ? (const float*)g_t : A_in;

    const int t  = threadIdx.x;
    const int tx = t & 15;       // 0..15
    const int ty = t >> 4;       // 0..15
    const int m0 = blockIdx.y * BM;
    const int e0 = blockIdx.x * BE;

    float acc[4][4];
#pragma unroll
    for (int i = 0; i < 4; i++)
#pragma unroll
        for (int j = 0; j < 4; j++) acc[i][j] = 0.f;

    for (int k0 = 0; k0 < KK; k0 += BKc) {
        // load A tile (64x32) and W tile (64x32), 512 float4 each half
#pragma unroll
        for (int l = 0; l < 2; l++) {
            int idx = t + l * 256;          // 0..511
            int r   = idx >> 3;             // 0..63
            int kk4 = (idx & 7) << 2;       // 0,4,...,28
            float4 a4 = *(const float4*)(A + (size_t)(m0 + r) * KK + k0 + kk4);
            As[kk4 + 0][r] = a4.x; As[kk4 + 1][r] = a4.y;
            As[kk4 + 2][r] = a4.z; As[kk4 + 3][r] = a4.w;
            float4 w4 = *(const float4*)(W + (size_t)(e0 + r) * KK + k0 + kk4);
            Ws[kk4 + 0][r] = w4.x; Ws[kk4 + 1][r] = w4.y;
            Ws[kk4 + 2][r] = w4.z; Ws[kk4 + 3][r] = w4.w;
        }
        __syncthreads();

#pragma unroll
        for (int kk = 0; kk < BKc; kk++) {
            float4 af = *(const float4*)&As[kk][ty << 2];
            float4 wf = *(const float4*)&Ws[kk][tx << 2];
            float a[4] = {af.x, af.y, af.z, af.w};
            float w[4] = {wf.x, wf.y, wf.z, wf.w};
#pragma unroll
            for (int i = 0; i < 4; i++)
#pragma unroll
                for (int j = 0; j < 4; j++) acc[i][j] += a[i] * w[j];
        }
        __syncthreads();
    }

    // epilogue
#pragma unroll
    for (int i = 0; i < 4; i++) {
        int m = m0 + (ty << 2) + i;
        int b = m >> 10;          // /N
        int n = m & 1023;
#pragma unroll
        for (int j = 0; j < 4; j++) {
            int e = e0 + (tx << 2) + j;
            float v = acc[i][j];
            if (MODE == 0) {
                int h = e >> 5, d = e & 31;
                g_q[(((b * HH + h) * NN + n) << 5) + d] = v * QSCALE;
            } else if (MODE == 1) {
                if (e < 256) {
                    int h = e >> 5, d = e & 31;
                    g_k[(((b * HH + h) * NN + n) << 5) + d] = v;
                } else {
                    int e2 = e - 256;
                    int h = e2 >> 5, d = e2 & 31;
                    g_v[(((b * HH + h) * NN + n) << 5) + d] = v;
                }
            } else if (MODE == 2) {
                float z = v + bvec[e];
                g_gate[(size_t)m * DQ + e] = 1.f / (1.f + __expf(-z));
            } else {
                C[(size_t)m * DQ + e] = v + bvec[e];
            }
        }
    }
}

// ---------------- attention: one warp per query row ----------------
// grid: (N/8, B*H), block 256 (8 warps). Online softmax over j in tiles of 32.
__global__ __launch_bounds__(256, 4) void attn_kernel(
    const float* __restrict__ bias, const float* __restrict__ mask)
{
    const int warp = threadIdx.x >> 5;
    const int lane = threadIdx.x & 31;
    const int bh = blockIdx.y;
    const int b  = bh >> 3;      // /H
    const int h  = bh & 7;
    const int i  = blockIdx.x * 8 + warp;

    // q row (32 floats) fully replicated per lane (uniform LDG -> broadcast)
    const float* qrow = g_q + ((size_t)(bh * NN + i) << 5);
    float qv[32];
#pragma unroll
    for (int tt = 0; tt < 8; tt++) {
        float4 f = *(const float4*)(qrow + (tt << 2));
        qv[4 * tt + 0] = f.x; qv[4 * tt + 1] = f.y;
        qv[4 * tt + 2] = f.z; qv[4 * tt + 3] = f.w;
    }
    const bool rowvalid = mask[b * NN + i] > 0.f;
    const float* krows = g_k + ((size_t)bh << 15);   // bh * N * D
    const float* vrows = g_v + ((size_t)bh << 15);
    const float* brow  = bias + ((size_t)(bh * NN + i) << 10);
    const float* mrow  = mask + b * NN;

    float m_run = -FLT_MAX, l_run = 0.f, acc = 0.f;

    for (int j0 = 0; j0 < NN; j0 += 32) {
        const int j = j0 + lane;
        float s = brow[j];
        const float4* kr = (const float4*)(krows + ((size_t)j << 5));
#pragma unroll
        for (int tt = 0; tt < 8; tt++) {
            float4 f = kr[tt];
            s += qv[4 * tt + 0] * f.x + qv[4 * tt + 1] * f.y
               + qv[4 * tt + 2] * f.z + qv[4 * tt + 3] * f.w;
        }
        if (!(rowvalid && mrow[j] > 0.f)) s = -FLT_MAX;

        // tile max
        float tm = s;
#pragma unroll
        for (int o = 16; o; o >>= 1) tm = fmaxf(tm, __shfl_xor_sync(0xffffffffu, tm, o));
        float m_new = fmaxf(m_run, tm);
        float p = __expf(s - m_new);
        float alpha = __expf(m_run - m_new);
        float ps = p;
#pragma unroll
        for (int o = 16; o; o >>= 1) ps += __shfl_xor_sync(0xffffffffu, ps, o);
        l_run = l_run * alpha + ps;
        acc *= alpha;

        // acc[d=lane] += sum_jj p_jj * v[j0+jj][lane]  (coalesced V loads)
#pragma unroll
        for (int jj = 0; jj < 32; jj++) {
            float pj = __shfl_sync(0xffffffffu, p, jj);
            acc += pj * vrows[((size_t)(j0 + jj) << 5) + lane];
        }
        m_run = m_new;
    }

    float o = acc / l_run;
    int m = b * NN + i;
    int e = (h << 5) + lane;
    size_t oi = (size_t)m * DQ + e;
    g_t[oi] = o * g_gate[oi];
}

extern "C" void kernel_launch(void* const* d_in, const int* in_sizes, int n_in,
                              void* d_out, int out_size)
{
    const float* x    = (const float*)d_in[0];
    const float* mask = (const float*)d_in[1];
    const float* bias = (const float*)d_in[2];
    const float* Wq   = (const float*)d_in[3];
    const float* Wkv  = (const float*)d_in[4];
    const float* Wo   = (const float*)d_in[5];
    const float* bo   = (const float*)d_in[6];
    const float* Wg   = (const float*)d_in[7];
    const float* bg   = (const float*)d_in[8];
    float* out = (float*)d_out;

    dim3 blk(256);
    // Q projection: E=256
    gemm_kernel<0><<<dim3(256 / BE, MM / BM), blk>>>(x, Wq, nullptr, nullptr);
    // KV projection: E=512
    gemm_kernel<1><<<dim3(512 / BE, MM / BM), blk>>>(x, Wkv, nullptr, nullptr);
    // Gate projection: E=256
    gemm_kernel<2><<<dim3(256 / BE, MM / BM), blk>>>(x, Wg, bg, nullptr);
    // Attention (+ gating)
    attn_kernel<<<dim3(NN / 8, BB * HH), blk>>>(bias, mask);
    // Output projection (reads g_t internally)
    gemm_kernel<3><<<dim3(256 / BE, MM / BM), blk>>>(nullptr, Wo, bo, out);
}

// round 5
// speedup vs baseline: 7.0772x; 7.0772x over previous
#include <cuda_runtime.h>
#include <float.h>
#include <math.h>
#include <stdint.h>

// Problem constants
#define BB 4
#define NN 1024
#define DQ 256
#define HH 8
#define DD 32
#define MM (BB * NN)          // 4096 rows
#define KK 256                 // inner dim for all projections
#define QSCALE 0.17677669529663687f  // 32^-0.5

// -------- scratch (no cudaMalloc allowed) --------
__device__ float g_q[BB * HH * NN * DD];     // [bh, n, d], pre-scaled
__device__ float g_k[BB * HH * NN * DD];
__device__ float g_v[BB * HH * NN * DD];
__device__ float g_gate[MM * DQ];            // sigmoid(x Wg^T + bg)
__device__ float g_t[MM * DQ];               // gated attention output

// ---------------- helpers ----------------
__device__ __forceinline__ uint32_t f2tf32(float f) {
    uint32_t u;
    asm("cvt.rna.tf32.f32 %0, %1;" : "=r"(u) : "f"(f));
    return u;
}

__device__ __forceinline__ void mma_tf32(float d[4], const uint32_t a[4],
                                         uint32_t b0, uint32_t b1) {
    asm volatile(
        "mma.sync.aligned.m16n8k8.row.col.f32.tf32.tf32.f32 "
        "{%0,%1,%2,%3}, {%4,%5,%6,%7}, {%8,%9}, {%0,%1,%2,%3};\n"
        : "+f"(d[0]), "+f"(d[1]), "+f"(d[2]), "+f"(d[3])
        : "r"(a[0]), "r"(a[1]), "r"(a[2]), "r"(a[3]), "r"(b0), "r"(b1));
}

// ---------------- tiled GEMM: C[m,e] = sum_k A[m,k] * W[e,k] ----------------
#define BM 64
#define BE 64
#define BKc 32

// MODE: 0=Q proj, 1=KV proj, 2=Gate proj, 3=Output proj (A read from g_t)
template <int MODE>
__global__ __launch_bounds__(256, 4) void gemm_kernel(
    const float* __restrict__ A_in, const float* __restrict__ W,
    const float* __restrict__ bvec, float* __restrict__ C)
{
    __shared__ float As[BKc][BM];
    __shared__ float Ws[BKc][BE];

    const float* A = (MODE == 3) ? (const float*)g_t : A_in;

    const int t  = threadIdx.x;
    const int tx = t & 15;
    const int ty = t >> 4;
    const int m0 = blockIdx.y * BM;
    const int e0 = blockIdx.x * BE;

    float acc[4][4];
#pragma unroll
    for (int i = 0; i < 4; i++)
#pragma unroll
        for (int j = 0; j < 4; j++) acc[i][j] = 0.f;

    for (int k0 = 0; k0 < KK; k0 += BKc) {
#pragma unroll
        for (int l = 0; l < 2; l++) {
            int idx = t + l * 256;
            int r   = idx >> 3;
            int kk4 = (idx & 7) << 2;
            float4 a4 = *(const float4*)(A + (size_t)(m0 + r) * KK + k0 + kk4);
            As[kk4 + 0][r] = a4.x; As[kk4 + 1][r] = a4.y;
            As[kk4 + 2][r] = a4.z; As[kk4 + 3][r] = a4.w;
            float4 w4 = *(const float4*)(W + (size_t)(e0 + r) * KK + k0 + kk4);
            Ws[kk4 + 0][r] = w4.x; Ws[kk4 + 1][r] = w4.y;
            Ws[kk4 + 2][r] = w4.z; Ws[kk4 + 3][r] = w4.w;
        }
        __syncthreads();

#pragma unroll
        for (int kk = 0; kk < BKc; kk++) {
            float4 af = *(const float4*)&As[kk][ty << 2];
            float4 wf = *(const float4*)&Ws[kk][tx << 2];
            float a[4] = {af.x, af.y, af.z, af.w};
            float w[4] = {wf.x, wf.y, wf.z, wf.w};
#pragma unroll
            for (int i = 0; i < 4; i++)
#pragma unroll
                for (int j = 0; j < 4; j++) acc[i][j] += a[i] * w[j];
        }
        __syncthreads();
    }

#pragma unroll
    for (int i = 0; i < 4; i++) {
        int m = m0 + (ty << 2) + i;
        int b = m >> 10;
        int n = m & 1023;
#pragma unroll
        for (int j = 0; j < 4; j++) {
            int e = e0 + (tx << 2) + j;
            float v = acc[i][j];
            if (MODE == 0) {
                int h = e >> 5, d = e & 31;
                g_q[(((b * HH + h) * NN + n) << 5) + d] = v * QSCALE;
            } else if (MODE == 1) {
                if (e < 256) {
                    int h = e >> 5, d = e & 31;
                    g_k[(((b * HH + h) * NN + n) << 5) + d] = v;
                } else {
                    int e2 = e - 256;
                    int h = e2 >> 5, d = e2 & 31;
                    g_v[(((b * HH + h) * NN + n) << 5) + d] = v;
                }
            } else if (MODE == 2) {
                float z = v + bvec[e];
                g_gate[(size_t)m * DQ + e] = 1.f / (1.f + __expf(-z));
            } else {
                C[(size_t)m * DQ + e] = v + bvec[e];
            }
        }
    }
}

// ---------------- attention via mma.sync tf32 ----------------
// Block = 256 threads (8 warps), handles 128 query rows of one (b,h).
// Each warp owns a 16-row stripe. j swept in tiles of 64.
// smem tiles 64x32. K stride 36 -> B-frag banks 4g+c4 (conflict-free).
//                   V stride 40 -> B-frag banks 8c4+g (conflict-free).
#define K_STRIDE 36
#define V_STRIDE 40

__global__ __launch_bounds__(256, 2) void attn_mma_kernel(
    const float* __restrict__ bias, const float* __restrict__ mask)
{
    __shared__ float Ks[64 * K_STRIDE];
    __shared__ float Vs[64 * V_STRIDE];

    const int t    = threadIdx.x;
    const int warp = t >> 5;
    const int lane = t & 31;
    const int g    = lane >> 2;     // group id 0..7
    const int c4   = lane & 3;      // thread-in-group

    const int bh = blockIdx.y;
    const int b  = bh >> 3;
    const int h  = bh & 7;
    const int i0 = blockIdx.x * 128;
    const int row0 = i0 + warp * 16 + g;   // rows row0 and row0+8

    // ---- Q fragments (tf32), held in registers for whole kernel ----
    const float* qbase = g_q + ((size_t)(bh * NN) << 5);
    uint32_t qa[4][4];
#pragma unroll
    for (int kk = 0; kk < 4; kk++) {
        qa[kk][0] = f2tf32(qbase[((size_t)row0 << 5) + kk * 8 + c4]);
        qa[kk][1] = f2tf32(qbase[((size_t)(row0 + 8) << 5) + kk * 8 + c4]);
        qa[kk][2] = f2tf32(qbase[((size_t)row0 << 5) + kk * 8 + c4 + 4]);
        qa[kk][3] = f2tf32(qbase[((size_t)(row0 + 8) << 5) + kk * 8 + c4 + 4]);
    }

    const bool rv0 = mask[b * NN + row0] > 0.f;
    const bool rv1 = mask[b * NN + row0 + 8] > 0.f;

    const float* Kg = g_k + ((size_t)bh << 15);
    const float* Vg = g_v + ((size_t)bh << 15);
    const float* bias0 = bias + ((size_t)(bh * NN + row0) << 10);
    const float* bias1 = bias0 + (8 << 10);
    const float* mrow  = mask + b * NN;

    float m0 = -1e30f, m1 = -1e30f, l0 = 0.f, l1 = 0.f;
    float o[4][4];
#pragma unroll
    for (int nt = 0; nt < 4; nt++)
#pragma unroll
        for (int r = 0; r < 4; r++) o[nt][r] = 0.f;

    const int lA = (lane & 28) | (c4 >> 1);
    const int lB = lA | 2;
    const bool odd = (lane & 1);

    for (int j0 = 0; j0 < NN; j0 += 64) {
        __syncthreads();
        // cooperative K/V tile load (convert to tf32 bits at store time)
#pragma unroll
        for (int q = 0; q < 2; q++) {
            int id = t + (q << 8);
            int r  = id >> 3;
            int dc = (id & 7) << 2;
            float4 kf = *(const float4*)(Kg + ((size_t)(j0 + r) << 5) + dc);
            float4 vf = *(const float4*)(Vg + ((size_t)(j0 + r) << 5) + dc);
            float4 kc, vc;
            kc.x = __uint_as_float(f2tf32(kf.x));
            kc.y = __uint_as_float(f2tf32(kf.y));
            kc.z = __uint_as_float(f2tf32(kf.z));
            kc.w = __uint_as_float(f2tf32(kf.w));
            vc.x = __uint_as_float(f2tf32(vf.x));
            vc.y = __uint_as_float(f2tf32(vf.y));
            vc.z = __uint_as_float(f2tf32(vf.z));
            vc.w = __uint_as_float(f2tf32(vf.w));
            *(float4*)&Ks[r * K_STRIDE + dc] = kc;
            *(float4*)&Vs[r * V_STRIDE + dc] = vc;
        }
        __syncthreads();

        // ---- S = Q K^T for this warp's 16 rows x 64 cols ----
        float s[8][4];
#pragma unroll
        for (int nt = 0; nt < 8; nt++) {
            s[nt][0] = s[nt][1] = s[nt][2] = s[nt][3] = 0.f;
#pragma unroll
            for (int kk = 0; kk < 4; kk++) {
                uint32_t b0 = __float_as_uint(Ks[(nt * 8 + g) * K_STRIDE + kk * 8 + c4]);
                uint32_t b1 = __float_as_uint(Ks[(nt * 8 + g) * K_STRIDE + kk * 8 + c4 + 4]);
                mma_tf32(s[nt], qa[kk], b0, b1);
            }
        }

        // ---- bias + mask ----
#pragma unroll
        for (int nt = 0; nt < 8; nt++) {
            int jc = j0 + nt * 8 + (c4 << 1);
            float2 bz0 = *(const float2*)(bias0 + jc);
            float2 bz1 = *(const float2*)(bias1 + jc);
            float2 mk  = *(const float2*)(mrow + jc);
            bool cx = mk.x > 0.f, cy = mk.y > 0.f;
            s[nt][0] = (rv0 && cx) ? s[nt][0] + bz0.x : -1e30f;
            s[nt][1] = (rv0 && cy) ? s[nt][1] + bz0.y : -1e30f;
            s[nt][2] = (rv1 && cx) ? s[nt][2] + bz1.x : -1e30f;
            s[nt][3] = (rv1 && cy) ? s[nt][3] + bz1.y : -1e30f;
        }

        // ---- online softmax ----
        float tm0 = -1e30f, tm1 = -1e30f;
#pragma unroll
        for (int nt = 0; nt < 8; nt++) {
            tm0 = fmaxf(tm0, fmaxf(s[nt][0], s[nt][1]));
            tm1 = fmaxf(tm1, fmaxf(s[nt][2], s[nt][3]));
        }
        tm0 = fmaxf(tm0, __shfl_xor_sync(0xffffffffu, tm0, 1));
        tm0 = fmaxf(tm0, __shfl_xor_sync(0xffffffffu, tm0, 2));
        tm1 = fmaxf(tm1, __shfl_xor_sync(0xffffffffu, tm1, 1));
        tm1 = fmaxf(tm1, __shfl_xor_sync(0xffffffffu, tm1, 2));

        float mn0 = fmaxf(m0, tm0), mn1 = fmaxf(m1, tm1);
        float al0 = __expf(m0 - mn0), al1 = __expf(m1 - mn1);

        float ps0 = 0.f, ps1 = 0.f;
#pragma unroll
        for (int nt = 0; nt < 8; nt++) {
            s[nt][0] = __expf(s[nt][0] - mn0);
            s[nt][1] = __expf(s[nt][1] - mn0);
            s[nt][2] = __expf(s[nt][2] - mn1);
            s[nt][3] = __expf(s[nt][3] - mn1);
            ps0 += s[nt][0] + s[nt][1];
            ps1 += s[nt][2] + s[nt][3];
        }
        ps0 += __shfl_xor_sync(0xffffffffu, ps0, 1);
        ps0 += __shfl_xor_sync(0xffffffffu, ps0, 2);
        ps1 += __shfl_xor_sync(0xffffffffu, ps1, 1);
        ps1 += __shfl_xor_sync(0xffffffffu, ps1, 2);
        l0 = l0 * al0 + ps0;
        l1 = l1 * al1 + ps1;
        m0 = mn0; m1 = mn1;

#pragma unroll
        for (int nt = 0; nt < 4; nt++) {
            o[nt][0] *= al0; o[nt][1] *= al0;
            o[nt][2] *= al1; o[nt][3] *= al1;
        }

        // convert P to tf32 bits in place
#pragma unroll
        for (int nt = 0; nt < 8; nt++) {
            s[nt][0] = __uint_as_float(f2tf32(s[nt][0]));
            s[nt][1] = __uint_as_float(f2tf32(s[nt][1]));
            s[nt][2] = __uint_as_float(f2tf32(s[nt][2]));
            s[nt][3] = __uint_as_float(f2tf32(s[nt][3]));
        }

        // ---- O += P V  (P C-layout -> A-frags via shfl) ----
#pragma unroll
        for (int kk = 0; kk < 8; kk++) {
            uint32_t a[4];
#pragma unroll
            for (int hv = 0; hv < 2; hv++) {
                int src = hv ? lB : lA;
                float w0 = __shfl_sync(0xffffffffu, s[kk][0], src);
                float w1 = __shfl_sync(0xffffffffu, s[kk][1], src);
                float w2 = __shfl_sync(0xffffffffu, s[kk][2], src);
                float w3 = __shfl_sync(0xffffffffu, s[kk][3], src);
                a[hv * 2 + 0] = __float_as_uint(odd ? w1 : w0);
                a[hv * 2 + 1] = __float_as_uint(odd ? w3 : w2);
            }
#pragma unroll
            for (int nt = 0; nt < 4; nt++) {
                uint32_t b0 = __float_as_uint(Vs[(kk * 8 + c4) * V_STRIDE + nt * 8 + g]);
                uint32_t b1 = __float_as_uint(Vs[(kk * 8 + c4 + 4) * V_STRIDE + nt * 8 + g]);
                mma_tf32(o[nt], a, b0, b1);
            }
        }
    }

    // ---- epilogue: normalize, gate, store ----
    float inv0 = 1.f / l0, inv1 = 1.f / l1;
    size_t mr0 = (size_t)(b * NN + row0) * DQ + h * 32;
    size_t mr1 = mr0 + (size_t)8 * DQ;
#pragma unroll
    for (int nt = 0; nt < 4; nt++) {
        int dc = nt * 8 + (c4 << 1);
        float2 gt0 = *(const float2*)(g_gate + mr0 + dc);
        float2 gt1 = *(const float2*)(g_gate + mr1 + dc);
        float2 r0, r1;
        r0.x = o[nt][0] * inv0 * gt0.x;
        r0.y = o[nt][1] * inv0 * gt0.y;
        r1.x = o[nt][2] * inv1 * gt1.x;
        r1.y = o[nt][3] * inv1 * gt1.y;
        *(float2*)(g_t + mr0 + dc) = r0;
        *(float2*)(g_t + mr1 + dc) = r1;
    }
}

extern "C" void kernel_launch(void* const* d_in, const int* in_sizes, int n_in,
                              void* d_out, int out_size)
{
    const float* x    = (const float*)d_in[0];
    const float* mask = (const float*)d_in[1];
    const float* bias = (const float*)d_in[2];
    const float* Wq   = (const float*)d_in[3];
    const float* Wkv  = (const float*)d_in[4];
    const float* Wo   = (const float*)d_in[5];
    const float* bo   = (const float*)d_in[6];
    const float* Wg   = (const float*)d_in[7];
    const float* bg   = (const float*)d_in[8];
    float* out = (float*)d_out;

    dim3 blk(256);
    gemm_kernel<0><<<dim3(256 / BE, MM / BM), blk>>>(x, Wq, nullptr, nullptr);
    gemm_kernel<1><<<dim3(512 / BE, MM / BM), blk>>>(x, Wkv, nullptr, nullptr);
    gemm_kernel<2><<<dim3(256 / BE, MM / BM), blk>>>(x, Wg, bg, nullptr);
    attn_mma_kernel<<<dim3(NN / 128, BB * HH), blk>>>(bias, mask);
    gemm_kernel<3><<<dim3(256 / BE, MM / BM), blk>>>(nullptr, Wo, bo, out);
}

// round 7
// speedup vs baseline: 11.4308x; 1.6151x over previous
#include <cuda_runtime.h>
#include <float.h>
#include <math.h>
#include <stdint.h>

// Problem constants
#define BB 4
#define NN 1024
#define DQ 256
#define HH 8
#define DD 32
#define MM (BB * NN)          // 4096 rows
#define KK 256                 // inner dim for all projections
#define QSCALE 0.17677669529663687f  // 32^-0.5

// -------- scratch (no cudaMalloc allowed) --------
__device__ float g_q[BB * HH * NN * DD];     // [bh, n, d], pre-scaled
__device__ float g_k[BB * HH * NN * DD];
__device__ float g_v[BB * HH * NN * DD];
__device__ float g_gate[MM * DQ];            // sigmoid(x Wg^T + bg)
__device__ float g_t[MM * DQ];               // gated attention output

// ---------------- helpers ----------------
__device__ __forceinline__ uint32_t f2tf32(float f) {
    uint32_t u;
    asm("cvt.rna.tf32.f32 %0, %1;" : "=r"(u) : "f"(f));
    return u;
}

__device__ __forceinline__ void mma_tf32(float d[4], const uint32_t a[4],
                                         uint32_t b0, uint32_t b1) {
    asm volatile(
        "mma.sync.aligned.m16n8k8.row.col.f32.tf32.tf32.f32 "
        "{%0,%1,%2,%3}, {%4,%5,%6,%7}, {%8,%9}, {%0,%1,%2,%3};\n"
        : "+f"(d[0]), "+f"(d[1]), "+f"(d[2]), "+f"(d[3])
        : "r"(a[0]), "r"(a[1]), "r"(a[2]), "r"(a[3]), "r"(b0), "r"(b1));
}

// ---------------- TF32 projection GEMM ----------------
// C[m,e] = sum_k A[m,k] * W[e,k].  Block: 128 m-rows x 64 e-cols, 8 warps,
// each warp 16x64.  k-chunks of 32.  smem stride 36 -> conflict-free frags.
// KIND 0: fused QKV+Gate (virtual E=1024, W chosen per e-block)
// KIND 1: output projection (A = g_t, writes out + bo)
#define PSTRIDE 36

template <int KIND>
__global__ __launch_bounds__(256, 3) void proj_kernel(
    const float* __restrict__ A_in,
    const float* __restrict__ Wq, const float* __restrict__ Wkv,
    const float* __restrict__ Wg, const float* __restrict__ bg,
    const float* __restrict__ bo, float* __restrict__ out)
{
    __shared__ float As[128 * PSTRIDE];
    __shared__ float Bs[64 * PSTRIDE];

    const int t    = threadIdx.x;
    const int warp = t >> 5;
    const int lane = t & 31;
    const int g    = lane >> 2;
    const int c4   = lane & 3;
    const int m0   = blockIdx.y * 128;
    const int e0   = blockIdx.x * 64;

    const float* A;
    const float* Wt;
    if (KIND == 0) {
        A = A_in;
        if (e0 < 256)      Wt = Wq  + (size_t)e0 * KK;
        else if (e0 < 768) Wt = Wkv + (size_t)(e0 - 256) * KK;
        else               Wt = Wg  + (size_t)(e0 - 768) * KK;
    } else {
        A = (const float*)g_t;
        Wt = Wq + (size_t)e0 * KK;   // Wq slot carries Wo for KIND 1
    }

    float s[8][4];
#pragma unroll
    for (int nt = 0; nt < 8; nt++)
        s[nt][0] = s[nt][1] = s[nt][2] = s[nt][3] = 0.f;

    const int row0 = warp * 16 + g;

    for (int k0 = 0; k0 < KK; k0 += 32) {
        __syncthreads();
        // A tile: 128x32 = 1024 float4, 4 per thread
#pragma unroll
        for (int l = 0; l < 4; l++) {
            int idx = t + (l << 8);
            int r   = idx >> 3;
            int c   = (idx & 7) << 2;
            float4 a4 = *(const float4*)(A + (size_t)(m0 + r) * KK + k0 + c);
            float4 ac;
            ac.x = __uint_as_float(f2tf32(a4.x));
            ac.y = __uint_as_float(f2tf32(a4.y));
            ac.z = __uint_as_float(f2tf32(a4.z));
            ac.w = __uint_as_float(f2tf32(a4.w));
            *(float4*)&As[r * PSTRIDE + c] = ac;
        }
        // W tile: 64x32 = 512 float4, 2 per thread
#pragma unroll
        for (int l = 0; l < 2; l++) {
            int idx = t + (l << 8);
            int r   = idx >> 3;
            int c   = (idx & 7) << 2;
            float4 w4 = *(const float4*)(Wt + (size_t)r * KK + k0 + c);
            float4 wc;
            wc.x = __uint_as_float(f2tf32(w4.x));
            wc.y = __uint_as_float(f2tf32(w4.y));
            wc.z = __uint_as_float(f2tf32(w4.z));
            wc.w = __uint_as_float(f2tf32(w4.w));
            *(float4*)&Bs[r * PSTRIDE + c] = wc;
        }
        __syncthreads();

#pragma unroll
        for (int kk = 0; kk < 4; kk++) {
            uint32_t a[4];
            a[0] = __float_as_uint(As[row0 * PSTRIDE + kk * 8 + c4]);
            a[1] = __float_as_uint(As[(row0 + 8) * PSTRIDE + kk * 8 + c4]);
            a[2] = __float_as_uint(As[row0 * PSTRIDE + kk * 8 + c4 + 4]);
            a[3] = __float_as_uint(As[(row0 + 8) * PSTRIDE + kk * 8 + c4 + 4]);
#pragma unroll
            for (int nt = 0; nt < 8; nt++) {
                uint32_t b0 = __float_as_uint(Bs[(nt * 8 + g) * PSTRIDE + kk * 8 + c4]);
                uint32_t b1 = __float_as_uint(Bs[(nt * 8 + g) * PSTRIDE + kk * 8 + c4 + 4]);
                mma_tf32(s[nt], a, b0, b1);
            }
        }
    }

    // ---- epilogue ----
#pragma unroll
    for (int half = 0; half < 2; half++) {
        int m = m0 + row0 + half * 8;
        int b = m >> 10;
        int n = m & 1023;
#pragma unroll
        for (int nt = 0; nt < 8; nt++) {
            int e = e0 + nt * 8 + (c4 << 1);
            float v0 = half ? s[nt][2] : s[nt][0];
            float v1 = half ? s[nt][3] : s[nt][1];
            if (KIND == 1) {
                float2 r;
                r.x = v0 + bo[e];
                r.y = v1 + bo[e + 1];
                *(float2*)(out + (size_t)m * DQ + e) = r;
            } else if (e0 < 256) {
                int h = e >> 5, d = e & 31;
                float2 r; r.x = v0 * QSCALE; r.y = v1 * QSCALE;
                *(float2*)(g_q + (((size_t)(b * HH + h) * NN + n) << 5) + d) = r;
            } else if (e0 < 512) {
                int e2 = e - 256;
                int h = e2 >> 5, d = e2 & 31;
                float2 r; r.x = v0; r.y = v1;
                *(float2*)(g_k + (((size_t)(b * HH + h) * NN + n) << 5) + d) = r;
            } else if (e0 < 768) {
                int e2 = e - 512;
                int h = e2 >> 5, d = e2 & 31;
                float2 r; r.x = v0; r.y = v1;
                *(float2*)(g_v + (((size_t)(b * HH + h) * NN + n) << 5) + d) = r;
            } else {
                int e2 = e - 768;
                float z0 = v0 + bg[e2];
                float z1 = v1 + bg[e2 + 1];
                float2 r;
                r.x = 1.f / (1.f + __expf(-z0));
                r.y = 1.f / (1.f + __expf(-z1));
                *(float2*)(g_gate + (size_t)m * DQ + e2) = r;
            }
        }
    }
}

// ---------------- attention via mma.sync tf32 (unchanged from R5) ----------------
#define K_STRIDE 36
#define V_STRIDE 40

__global__ __launch_bounds__(256, 2) void attn_mma_kernel(
    const float* __restrict__ bias, const float* __restrict__ mask)
{
    __shared__ float Ks[64 * K_STRIDE];
    __shared__ float Vs[64 * V_STRIDE];

    const int t    = threadIdx.x;
    const int warp = t >> 5;
    const int lane = t & 31;
    const int g    = lane >> 2;
    const int c4   = lane & 3;

    const int bh = blockIdx.y;
    const int b  = bh >> 3;
    const int h  = bh & 7;
    const int i0 = blockIdx.x * 128;
    const int row0 = i0 + warp * 16 + g;

    const float* qbase = g_q + ((size_t)(bh * NN) << 5);
    uint32_t qa[4][4];
#pragma unroll
    for (int kk = 0; kk < 4; kk++) {
        qa[kk][0] = f2tf32(qbase[((size_t)row0 << 5) + kk * 8 + c4]);
        qa[kk][1] = f2tf32(qbase[((size_t)(row0 + 8) << 5) + kk * 8 + c4]);
        qa[kk][2] = f2tf32(qbase[((size_t)row0 << 5) + kk * 8 + c4 + 4]);
        qa[kk][3] = f2tf32(qbase[((size_t)(row0 + 8) << 5) + kk * 8 + c4 + 4]);
    }

    const bool rv0 = mask[b * NN + row0] > 0.f;
    const bool rv1 = mask[b * NN + row0 + 8] > 0.f;

    const float* Kg = g_k + ((size_t)bh << 15);
    const float* Vg = g_v + ((size_t)bh << 15);
    const float* bias0 = bias + ((size_t)(bh * NN + row0) << 10);
    const float* bias1 = bias0 + (8 << 10);
    const float* mrow  = mask + b * NN;

    float m0 = -1e30f, m1 = -1e30f, l0 = 0.f, l1 = 0.f;
    float o[4][4];
#pragma unroll
    for (int nt = 0; nt < 4; nt++)
#pragma unroll
        for (int r = 0; r < 4; r++) o[nt][r] = 0.f;

    const int lA = (lane & 28) | (c4 >> 1);
    const int lB = lA | 2;
    const bool odd = (lane & 1);

    for (int j0 = 0; j0 < NN; j0 += 64) {
        __syncthreads();
#pragma unroll
        for (int q = 0; q < 2; q++) {
            int id = t + (q << 8);
            int r  = id >> 3;
            int dc = (id & 7) << 2;
            float4 kf = *(const float4*)(Kg + ((size_t)(j0 + r) << 5) + dc);
            float4 vf = *(const float4*)(Vg + ((size_t)(j0 + r) << 5) + dc);
            float4 kc, vc;
            kc.x = __uint_as_float(f2tf32(kf.x));
            kc.y = __uint_as_float(f2tf32(kf.y));
            kc.z = __uint_as_float(f2tf32(kf.z));
            kc.w = __uint_as_float(f2tf32(kf.w));
            vc.x = __uint_as_float(f2tf32(vf.x));
            vc.y = __uint_as_float(f2tf32(vf.y));
            vc.z = __uint_as_float(f2tf32(vf.z));
            vc.w = __uint_as_float(f2tf32(vf.w));
            *(float4*)&Ks[r * K_STRIDE + dc] = kc;
            *(float4*)&Vs[r * V_STRIDE + dc] = vc;
        }
        __syncthreads();

        float s[8][4];
#pragma unroll
        for (int nt = 0; nt < 8; nt++) {
            s[nt][0] = s[nt][1] = s[nt][2] = s[nt][3] = 0.f;
#pragma unroll
            for (int kk = 0; kk < 4; kk++) {
                uint32_t b0 = __float_as_uint(Ks[(nt * 8 + g) * K_STRIDE + kk * 8 + c4]);
                uint32_t b1 = __float_as_uint(Ks[(nt * 8 + g) * K_STRIDE + kk * 8 + c4 + 4]);
                mma_tf32(s[nt], qa[kk], b0, b1);
            }
        }

#pragma unroll
        for (int nt = 0; nt < 8; nt++) {
            int jc = j0 + nt * 8 + (c4 << 1);
            float2 bz0 = *(const float2*)(bias0 + jc);
            float2 bz1 = *(const float2*)(bias1 + jc);
            float2 mk  = *(const float2*)(mrow + jc);
            bool cx = mk.x > 0.f, cy = mk.y > 0.f;
            s[nt][0] = (rv0 && cx) ? s[nt][0] + bz0.x : -1e30f;
            s[nt][1] = (rv0 && cy) ? s[nt][1] + bz0.y : -1e30f;
            s[nt][2] = (rv1 && cx) ? s[nt][2] + bz1.x : -1e30f;
            s[nt][3] = (rv1 && cy) ? s[nt][3] + bz1.y : -1e30f;
        }

        float tm0 = -1e30f, tm1 = -1e30f;
#pragma unroll
        for (int nt = 0; nt < 8; nt++) {
            tm0 = fmaxf(tm0, fmaxf(s[nt][0], s[nt][1]));
            tm1 = fmaxf(tm1, fmaxf(s[nt][2], s[nt][3]));
        }
        tm0 = fmaxf(tm0, __shfl_xor_sync(0xffffffffu, tm0, 1));
        tm0 = fmaxf(tm0, __shfl_xor_sync(0xffffffffu, tm0, 2));
        tm1 = fmaxf(tm1, __shfl_xor_sync(0xffffffffu, tm1, 1));
        tm1 = fmaxf(tm1, __shfl_xor_sync(0xffffffffu, tm1, 2));

        float mn0 = fmaxf(m0, tm0), mn1 = fmaxf(m1, tm1);
        float al0 = __expf(m0 - mn0), al1 = __expf(m1 - mn1);

        float ps0 = 0.f, ps1 = 0.f;
#pragma unroll
        for (int nt = 0; nt < 8; nt++) {
            s[nt][0] = __expf(s[nt][0] - mn0);
            s[nt][1] = __expf(s[nt][1] - mn0);
            s[nt][2] = __expf(s[nt][2] - mn1);
            s[nt][3] = __expf(s[nt][3] - mn1);
            ps0 += s[nt][0] + s[nt][1];
            ps1 += s[nt][2] + s[nt][3];
        }
        ps0 += __shfl_xor_sync(0xffffffffu, ps0, 1);
        ps0 += __shfl_xor_sync(0xffffffffu, ps0, 2);
        ps1 += __shfl_xor_sync(0xffffffffu, ps1, 1);
        ps1 += __shfl_xor_sync(0xffffffffu, ps1, 2);
        l0 = l0 * al0 + ps0;
        l1 = l1 * al1 + ps1;
        m0 = mn0; m1 = mn1;

#pragma unroll
        for (int nt = 0; nt < 4; nt++) {
            o[nt][0] *= al0; o[nt][1] *= al0;
            o[nt][2] *= al1; o[nt][3] *= al1;
        }

#pragma unroll
        for (int nt = 0; nt < 8; nt++) {
            s[nt][0] = __uint_as_float(f2tf32(s[nt][0]));
            s[nt][1] = __uint_as_float(f2tf32(s[nt][1]));
            s[nt][2] = __uint_as_float(f2tf32(s[nt][2]));
            s[nt][3] = __uint_as_float(f2tf32(s[nt][3]));
        }

#pragma unroll
        for (int kk = 0; kk < 8; kk++) {
            uint32_t a[4];
#pragma unroll
            for (int hv = 0; hv < 2; hv++) {
                int src = hv ? lB : lA;
                float w0 = __shfl_sync(0xffffffffu, s[kk][0], src);
                float w1 = __shfl_sync(0xffffffffu, s[kk][1], src);
                float w2 = __shfl_sync(0xffffffffu, s[kk][2], src);
                float w3 = __shfl_sync(0xffffffffu, s[kk][3], src);
                a[hv * 2 + 0] = __float_as_uint(odd ? w1 : w0);
                a[hv * 2 + 1] = __float_as_uint(odd ? w3 : w2);
            }
#pragma unroll
            for (int nt = 0; nt < 4; nt++) {
                uint32_t b0 = __float_as_uint(Vs[(kk * 8 + c4) * V_STRIDE + nt * 8 + g]);
                uint32_t b1 = __float_as_uint(Vs[(kk * 8 + c4 + 4) * V_STRIDE + nt * 8 + g]);
                mma_tf32(o[nt], a, b0, b1);
            }
        }
    }

    float inv0 = 1.f / l0, inv1 = 1.f / l1;
    size_t mr0 = (size_t)(b * NN + row0) * DQ + h * 32;
    size_t mr1 = mr0 + (size_t)8 * DQ;
#pragma unroll
    for (int nt = 0; nt < 4; nt++) {
        int dc = nt * 8 + (c4 << 1);
        float2 gt0 = *(const float2*)(g_gate + mr0 + dc);
        float2 gt1 = *(const float2*)(g_gate + mr1 + dc);
        float2 r0, r1;
        r0.x = o[nt][0] * inv0 * gt0.x;
        r0.y = o[nt][1] * inv0 * gt0.y;
        r1.x = o[nt][2] * inv1 * gt1.x;
        r1.y = o[nt][3] * inv1 * gt1.y;
        *(float2*)(g_t + mr0 + dc) = r0;
        *(float2*)(g_t + mr1 + dc) = r1;
    }
}

extern "C" void kernel_launch(void* const* d_in, const int* in_sizes, int n_in,
                              void* d_out, int out_size)
{
    const float* x    = (const float*)d_in[0];
    const float* mask = (const float*)d_in[1];
    const float* bias = (const float*)d_in[2];
    const float* Wq   = (const float*)d_in[3];
    const float* Wkv  = (const float*)d_in[4];
    const float* Wo   = (const float*)d_in[5];
    const float* bo   = (const float*)d_in[6];
    const float* Wg   = (const float*)d_in[7];
    const float* bg   = (const float*)d_in[8];
    float* out = (float*)d_out;

    dim3 blk(256);
    // Fused Q + KV + Gate projections (virtual E = 1024)
    proj_kernel<0><<<dim3(16, 32), blk>>>(x, Wq, Wkv, Wg, bg, nullptr, nullptr);
    // Attention (+ gating)
    attn_mma_kernel<<<dim3(NN / 128, BB * HH), blk>>>(bias, mask);
    // Output projection (A = g_t, W = Wo in the Wq slot)
    proj_kernel<1><<<dim3(4, 32), blk>>>(nullptr, Wo, nullptr, nullptr, nullptr, bo, out);
}

// round 8
// speedup vs baseline: 12.3160x; 1.0774x over previous
#include <cuda_runtime.h>
#include <float.h>
#include <math.h>
#include <stdint.h>

// Problem constants
#define BB 4
#define NN 1024
#define DQ 256
#define HH 8
#define DD 32
#define MM (BB * NN)          // 4096 rows
#define KK 256                 // inner dim for all projections
#define QSCALE 0.17677669529663687f  // 32^-0.5

// -------- scratch (no cudaMalloc allowed) --------
__device__ float g_q[BB * HH * NN * DD];     // [bh, n, d], pre-scaled
__device__ float g_k[BB * HH * NN * DD];
__device__ float g_v[BB * HH * NN * DD];
__device__ float g_gate[MM * DQ];            // sigmoid(x Wg^T + bg)
__device__ float g_t[MM * DQ];               // gated attention output

// ---------------- helpers ----------------
__device__ __forceinline__ uint32_t f2tf32(float f) {
    uint32_t u;
    asm("cvt.rna.tf32.f32 %0, %1;" : "=r"(u) : "f"(f));
    return u;
}

__device__ __forceinline__ void mma_tf32(float d[4], const uint32_t a[4],
                                         uint32_t b0, uint32_t b1) {
    asm volatile(
        "mma.sync.aligned.m16n8k8.row.col.f32.tf32.tf32.f32 "
        "{%0,%1,%2,%3}, {%4,%5,%6,%7}, {%8,%9}, {%0,%1,%2,%3};\n"
        : "+f"(d[0]), "+f"(d[1]), "+f"(d[2]), "+f"(d[3])
        : "r"(a[0]), "r"(a[1]), "r"(a[2]), "r"(a[3]), "r"(b0), "r"(b1));
}

// ---------------- TF32 projection GEMM ----------------
// C[m,e] = sum_k A[m,k] * W[e,k].
// Block: 128 threads (4 warps).  Warp tile: (16*SETS) m-rows x 64 e-cols.
// Block m-tile = 64*SETS, e-tile = 64.  k-chunks of 32, smem stride 36.
// KIND 0: fused QKV+Gate (virtual E=1024).  KIND 1: output proj (A = g_t).
#define PSTRIDE 36

template <int KIND, int SETS>
__global__ __launch_bounds__(128, 4) void proj_kernel(
    const float* __restrict__ A_in,
    const float* __restrict__ Wq, const float* __restrict__ Wkv,
    const float* __restrict__ Wg, const float* __restrict__ bg,
    const float* __restrict__ bo, float* __restrict__ out)
{
    __shared__ float As[64 * SETS * PSTRIDE];
    __shared__ float Bs[64 * PSTRIDE];

    const int t    = threadIdx.x;
    const int warp = t >> 5;
    const int lane = t & 31;
    const int g    = lane >> 2;
    const int c4   = lane & 3;
    const int m0   = blockIdx.y * (64 * SETS);
    const int e0   = blockIdx.x * 64;

    const float* A;
    const float* Wt;
    if (KIND == 0) {
        A = A_in;
        if (e0 < 256)      Wt = Wq  + (size_t)e0 * KK;
        else if (e0 < 768) Wt = Wkv + (size_t)(e0 - 256) * KK;
        else               Wt = Wg  + (size_t)(e0 - 768) * KK;
    } else {
        A = (const float*)g_t;
        Wt = Wq + (size_t)e0 * KK;   // Wq slot carries Wo for KIND 1
    }

    float s[SETS][8][4];
#pragma unroll
    for (int st = 0; st < SETS; st++)
#pragma unroll
        for (int nt = 0; nt < 8; nt++)
            s[st][nt][0] = s[st][nt][1] = s[st][nt][2] = s[st][nt][3] = 0.f;

    const int row0 = warp * (16 * SETS) + g;

    for (int k0 = 0; k0 < KK; k0 += 32) {
        __syncthreads();
        // A tile: (64*SETS)x32 floats = 512*SETS float4, 4*SETS per thread
#pragma unroll
        for (int l = 0; l < 4 * SETS; l++) {
            int idx = t + (l << 7);
            int r   = idx >> 3;
            int c   = (idx & 7) << 2;
            float4 a4 = *(const float4*)(A + (size_t)(m0 + r) * KK + k0 + c);
            float4 ac;
            ac.x = __uint_as_float(f2tf32(a4.x));
            ac.y = __uint_as_float(f2tf32(a4.y));
            ac.z = __uint_as_float(f2tf32(a4.z));
            ac.w = __uint_as_float(f2tf32(a4.w));
            *(float4*)&As[r * PSTRIDE + c] = ac;
        }
        // W tile: 64x32 = 512 float4, 4 per thread
#pragma unroll
        for (int l = 0; l < 4; l++) {
            int idx = t + (l << 7);
            int r   = idx >> 3;
            int c   = (idx & 7) << 2;
            float4 w4 = *(const float4*)(Wt + (size_t)r * KK + k0 + c);
            float4 wc;
            wc.x = __uint_as_float(f2tf32(w4.x));
            wc.y = __uint_as_float(f2tf32(w4.y));
            wc.z = __uint_as_float(f2tf32(w4.z));
            wc.w = __uint_as_float(f2tf32(w4.w));
            *(float4*)&Bs[r * PSTRIDE + c] = wc;
        }
        __syncthreads();

#pragma unroll
        for (int kk = 0; kk < 4; kk++) {
            uint32_t a[SETS][4];
#pragma unroll
            for (int st = 0; st < SETS; st++) {
                int rr = row0 + st * 16;
                a[st][0] = __float_as_uint(As[rr * PSTRIDE + kk * 8 + c4]);
                a[st][1] = __float_as_uint(As[(rr + 8) * PSTRIDE + kk * 8 + c4]);
                a[st][2] = __float_as_uint(As[rr * PSTRIDE + kk * 8 + c4 + 4]);
                a[st][3] = __float_as_uint(As[(rr + 8) * PSTRIDE + kk * 8 + c4 + 4]);
            }
#pragma unroll
            for (int nt = 0; nt < 8; nt++) {
                uint32_t b0 = __float_as_uint(Bs[(nt * 8 + g) * PSTRIDE + kk * 8 + c4]);
                uint32_t b1 = __float_as_uint(Bs[(nt * 8 + g) * PSTRIDE + kk * 8 + c4 + 4]);
#pragma unroll
                for (int st = 0; st < SETS; st++)
                    mma_tf32(s[st][nt], a[st], b0, b1);
            }
        }
    }

    // ---- epilogue ----
#pragma unroll
    for (int st = 0; st < SETS; st++) {
#pragma unroll
        for (int half = 0; half < 2; half++) {
            int m = m0 + row0 + st * 16 + half * 8;
            int b = m >> 10;
            int n = m & 1023;
#pragma unroll
            for (int nt = 0; nt < 8; nt++) {
                int e = e0 + nt * 8 + (c4 << 1);
                float v0 = half ? s[st][nt][2] : s[st][nt][0];
                float v1 = half ? s[st][nt][3] : s[st][nt][1];
                if (KIND == 1) {
                    float2 r;
                    r.x = v0 + bo[e];
                    r.y = v1 + bo[e + 1];
                    *(float2*)(out + (size_t)m * DQ + e) = r;
                } else if (e0 < 256) {
                    int h = e >> 5, d = e & 31;
                    float2 r; r.x = v0 * QSCALE; r.y = v1 * QSCALE;
                    *(float2*)(g_q + (((size_t)(b * HH + h) * NN + n) << 5) + d) = r;
                } else if (e0 < 512) {
                    int e2 = e - 256;
                    int h = e2 >> 5, d = e2 & 31;
                    float2 r; r.x = v0; r.y = v1;
                    *(float2*)(g_k + (((size_t)(b * HH + h) * NN + n) << 5) + d) = r;
                } else if (e0 < 768) {
                    int e2 = e - 512;
                    int h = e2 >> 5, d = e2 & 31;
                    float2 r; r.x = v0; r.y = v1;
                    *(float2*)(g_v + (((size_t)(b * HH + h) * NN + n) << 5) + d) = r;
                } else {
                    int e2 = e - 768;
                    float z0 = v0 + bg[e2];
                    float z1 = v1 + bg[e2 + 1];
                    float2 r;
                    r.x = 1.f / (1.f + __expf(-z0));
                    r.y = 1.f / (1.f + __expf(-z1));
                    *(float2*)(g_gate + (size_t)m * DQ + e2) = r;
                }
            }
        }
    }
}

// ---------------- attention via mma.sync tf32 ----------------
// Block = 128 threads (4 warps), 64 query rows of one (b,h); grid (16, 32).
// Each warp owns a 16-row stripe. j swept in tiles of 64.
#define K_STRIDE 36
#define V_STRIDE 40

__global__ __launch_bounds__(128, 4) void attn_mma_kernel(
    const float* __restrict__ bias, const float* __restrict__ mask)
{
    __shared__ float Ks[64 * K_STRIDE];
    __shared__ float Vs[64 * V_STRIDE];

    const int t    = threadIdx.x;
    const int warp = t >> 5;
    const int lane = t & 31;
    const int g    = lane >> 2;
    const int c4   = lane & 3;

    const int bh = blockIdx.y;
    const int b  = bh >> 3;
    const int h  = bh & 7;
    const int i0 = blockIdx.x * 64;
    const int row0 = i0 + warp * 16 + g;

    const float* qbase = g_q + ((size_t)(bh * NN) << 5);
    uint32_t qa[4][4];
#pragma unroll
    for (int kk = 0; kk < 4; kk++) {
        qa[kk][0] = f2tf32(qbase[((size_t)row0 << 5) + kk * 8 + c4]);
        qa[kk][1] = f2tf32(qbase[((size_t)(row0 + 8) << 5) + kk * 8 + c4]);
        qa[kk][2] = f2tf32(qbase[((size_t)row0 << 5) + kk * 8 + c4 + 4]);
        qa[kk][3] = f2tf32(qbase[((size_t)(row0 + 8) << 5) + kk * 8 + c4 + 4]);
    }

    const bool rv0 = mask[b * NN + row0] > 0.f;
    const bool rv1 = mask[b * NN + row0 + 8] > 0.f;

    const float* Kg = g_k + ((size_t)bh << 15);
    const float* Vg = g_v + ((size_t)bh << 15);
    const float* bias0 = bias + ((size_t)(bh * NN + row0) << 10);
    const float* bias1 = bias0 + (8 << 10);
    const float* mrow  = mask + b * NN;

    float m0 = -1e30f, m1 = -1e30f, l0 = 0.f, l1 = 0.f;
    float o[4][4];
#pragma unroll
    for (int nt = 0; nt < 4; nt++)
#pragma unroll
        for (int r = 0; r < 4; r++) o[nt][r] = 0.f;

    const int lA = (lane & 28) | (c4 >> 1);
    const int lB = lA | 2;
    const bool odd = (lane & 1);

    for (int j0 = 0; j0 < NN; j0 += 64) {
        __syncthreads();
        // cooperative K/V tile load: 64x32 = 512 float4 each, 4 per thread
#pragma unroll
        for (int q = 0; q < 4; q++) {
            int id = t + (q << 7);
            int r  = id >> 3;
            int dc = (id & 7) << 2;
            float4 kf = *(const float4*)(Kg + ((size_t)(j0 + r) << 5) + dc);
            float4 vf = *(const float4*)(Vg + ((size_t)(j0 + r) << 5) + dc);
            float4 kc, vc;
            kc.x = __uint_as_float(f2tf32(kf.x));
            kc.y = __uint_as_float(f2tf32(kf.y));
            kc.z = __uint_as_float(f2tf32(kf.z));
            kc.w = __uint_as_float(f2tf32(kf.w));
            vc.x = __uint_as_float(f2tf32(vf.x));
            vc.y = __uint_as_float(f2tf32(vf.y));
            vc.z = __uint_as_float(f2tf32(vf.z));
            vc.w = __uint_as_float(f2tf32(vf.w));
            *(float4*)&Ks[r * K_STRIDE + dc] = kc;
            *(float4*)&Vs[r * V_STRIDE + dc] = vc;
        }
        __syncthreads();

        float s[8][4];
#pragma unroll
        for (int nt = 0; nt < 8; nt++) {
            s[nt][0] = s[nt][1] = s[nt][2] = s[nt][3] = 0.f;
#pragma unroll
            for (int kk = 0; kk < 4; kk++) {
                uint32_t b0 = __float_as_uint(Ks[(nt * 8 + g) * K_STRIDE + kk * 8 + c4]);
                uint32_t b1 = __float_as_uint(Ks[(nt * 8 + g) * K_STRIDE + kk * 8 + c4 + 4]);
                mma_tf32(s[nt], qa[kk], b0, b1);
            }
        }

#pragma unroll
        for (int nt = 0; nt < 8; nt++) {
            int jc = j0 + nt * 8 + (c4 << 1);
            float2 bz0 = *(const float2*)(bias0 + jc);
            float2 bz1 = *(const float2*)(bias1 + jc);
            float2 mk  = *(const float2*)(mrow + jc);
            bool cx = mk.x > 0.f, cy = mk.y > 0.f;
            s[nt][0] = (rv0 && cx) ? s[nt][0] + bz0.x : -1e30f;
            s[nt][1] = (rv0 && cy) ? s[nt][1] + bz0.y : -1e30f;
            s[nt][2] = (rv1 && cx) ? s[nt][2] + bz1.x : -1e30f;
            s[nt][3] = (rv1 && cy) ? s[nt][3] + bz1.y : -1e30f;
        }

        float tm0 = -1e30f, tm1 = -1e30f;
#pragma unroll
        for (int nt = 0; nt < 8; nt++) {
            tm0 = fmaxf(tm0, fmaxf(s[nt][0], s[nt][1]));
            tm1 = fmaxf(tm1, fmaxf(s[nt][2], s[nt][3]));
        }
        tm0 = fmaxf(tm0, __shfl_xor_sync(0xffffffffu, tm0, 1));
        tm0 = fmaxf(tm0, __shfl_xor_sync(0xffffffffu, tm0, 2));
        tm1 = fmaxf(tm1, __shfl_xor_sync(0xffffffffu, tm1, 1));
        tm1 = fmaxf(tm1, __shfl_xor_sync(0xffffffffu, tm1, 2));

        float mn0 = fmaxf(m0, tm0), mn1 = fmaxf(m1, tm1);
        float al0 = __expf(m0 - mn0), al1 = __expf(m1 - mn1);

        float ps0 = 0.f, ps1 = 0.f;
#pragma unroll
        for (int nt = 0; nt < 8; nt++) {
            s[nt][0] = __expf(s[nt][0] - mn0);
            s[nt][1] = __expf(s[nt][1] - mn0);
            s[nt][2] = __expf(s[nt][2] - mn1);
            s[nt][3] = __expf(s[nt][3] - mn1);
            ps0 += s[nt][0] + s[nt][1];
            ps1 += s[nt][2] + s[nt][3];
        }
        ps0 += __shfl_xor_sync(0xffffffffu, ps0, 1);
        ps0 += __shfl_xor_sync(0xffffffffu, ps0, 2);
        ps1 += __shfl_xor_sync(0xffffffffu, ps1, 1);
        ps1 += __shfl_xor_sync(0xffffffffu, ps1, 2);
        l0 = l0 * al0 + ps0;
        l1 = l1 * al1 + ps1;
        m0 = mn0; m1 = mn1;

#pragma unroll
        for (int nt = 0; nt < 4; nt++) {
            o[nt][0] *= al0; o[nt][1] *= al0;
            o[nt][2] *= al1; o[nt][3] *= al1;
        }

#pragma unroll
        for (int nt = 0; nt < 8; nt++) {
            s[nt][0] = __uint_as_float(f2tf32(s[nt][0]));
            s[nt][1] = __uint_as_float(f2tf32(s[nt][1]));
            s[nt][2] = __uint_as_float(f2tf32(s[nt][2]));
            s[nt][3] = __uint_as_float(f2tf32(s[nt][3]));
        }

#pragma unroll
        for (int kk = 0; kk < 8; kk++) {
            uint32_t a[4];
#pragma unroll
            for (int hv = 0; hv < 2; hv++) {
                int src = hv ? lB : lA;
                float w0 = __shfl_sync(0xffffffffu, s[kk][0], src);
                float w1 = __shfl_sync(0xffffffffu, s[kk][1], src);
                float w2 = __shfl_sync(0xffffffffu, s[kk][2], src);
                float w3 = __shfl_sync(0xffffffffu, s[kk][3], src);
                a[hv * 2 + 0] = __float_as_uint(odd ? w1 : w0);
                a[hv * 2 + 1] = __float_as_uint(odd ? w3 : w2);
            }
#pragma unroll
            for (int nt = 0; nt < 4; nt++) {
                uint32_t b0 = __float_as_uint(Vs[(kk * 8 + c4) * V_STRIDE + nt * 8 + g]);
                uint32_t b1 = __float_as_uint(Vs[(kk * 8 + c4 + 4) * V_STRIDE + nt * 8 + g]);
                mma_tf32(o[nt], a, b0, b1);
            }
        }
    }

    float inv0 = 1.f / l0, inv1 = 1.f / l1;
    size_t mr0 = (size_t)(b * NN + row0) * DQ + h * 32;
    size_t mr1 = mr0 + (size_t)8 * DQ;
#pragma unroll
    for (int nt = 0; nt < 4; nt++) {
        int dc = nt * 8 + (c4 << 1);
        float2 gt0 = *(const float2*)(g_gate + mr0 + dc);
        float2 gt1 = *(const float2*)(g_gate + mr1 + dc);
        float2 r0, r1;
        r0.x = o[nt][0] * inv0 * gt0.x;
        r0.y = o[nt][1] * inv0 * gt0.y;
        r1.x = o[nt][2] * inv1 * gt1.x;
        r1.y = o[nt][3] * inv1 * gt1.y;
        *(float2*)(g_t + mr0 + dc) = r0;
        *(float2*)(g_t + mr1 + dc) = r1;
    }
}

extern "C" void kernel_launch(void* const* d_in, const int* in_sizes, int n_in,
                              void* d_out, int out_size)
{
    const float* x    = (const float*)d_in[0];
    const float* mask = (const float*)d_in[1];
    const float* bias = (const float*)d_in[2];
    const float* Wq   = (const float*)d_in[3];
    const float* Wkv  = (const float*)d_in[4];
    const float* Wo   = (const float*)d_in[5];
    const float* bo   = (const float*)d_in[6];
    const float* Wg   = (const float*)d_in[7];
    const float* bg   = (const float*)d_in[8];
    float* out = (float*)d_out;

    dim3 blk(128);
    // Fused Q + KV + Gate projections (virtual E = 1024), m-tile 128
    proj_kernel<0, 2><<<dim3(16, 32), blk>>>(x, Wq, Wkv, Wg, bg, nullptr, nullptr);
    // Attention (+ gating): 64 rows per block, all SMs covered
    attn_mma_kernel<<<dim3(NN / 64, BB * HH), blk>>>(bias, mask);
    // Output projection (A = g_t, W = Wo in the Wq slot), m-tile 64
    proj_kernel<1, 1><<<dim3(4, 64), blk>>>(nullptr, Wo, nullptr, nullptr, nullptr, bo, out);
}

// round 9
// speedup vs baseline: 12.9924x; 1.0549x over previous
#include <cuda_runtime.h>
#include <float.h>
#include <math.h>
#include <stdint.h>

// Problem constants
#define BB 4
#define NN 1024
#define DQ 256
#define HH 8
#define DD 32
#define MM (BB * NN)          // 4096 rows
#define KK 256                 // inner dim for all projections
#define QSCALE 0.17677669529663687f  // 32^-0.5

// -------- scratch (no cudaMalloc allowed) --------
__device__ float g_q[BB * HH * NN * DD];     // [bh, n, d], pre-scaled
__device__ float g_k[BB * HH * NN * DD];
__device__ float g_v[BB * HH * NN * DD];
__device__ float g_gate[MM * DQ];            // sigmoid(x Wg^T + bg)
__device__ float g_t[MM * DQ];               // gated attention output

// ---------------- helpers ----------------
__device__ __forceinline__ uint32_t f2tf32(float f) {
    uint32_t u;
    asm("cvt.rna.tf32.f32 %0, %1;" : "=r"(u) : "f"(f));
    return u;
}

__device__ __forceinline__ void mma_tf32(float d[4], const uint32_t a[4],
                                         uint32_t b0, uint32_t b1) {
    asm volatile(
        "mma.sync.aligned.m16n8k8.row.col.f32.tf32.tf32.f32 "
        "{%0,%1,%2,%3}, {%4,%5,%6,%7}, {%8,%9}, {%0,%1,%2,%3};\n"
        : "+f"(d[0]), "+f"(d[1]), "+f"(d[2]), "+f"(d[3])
        : "r"(a[0]), "r"(a[1]), "r"(a[2]), "r"(a[3]), "r"(b0), "r"(b1));
}

// ---------------- TF32 projection GEMM (unchanged from R8) ----------------
#define PSTRIDE 36

template <int KIND, int SETS>
__global__ __launch_bounds__(128, 4) void proj_kernel(
    const float* __restrict__ A_in,
    const float* __restrict__ Wq, const float* __restrict__ Wkv,
    const float* __restrict__ Wg, const float* __restrict__ bg,
    const float* __restrict__ bo, float* __restrict__ out)
{
    __shared__ float As[64 * SETS * PSTRIDE];
    __shared__ float Bs[64 * PSTRIDE];

    const int t    = threadIdx.x;
    const int warp = t >> 5;
    const int lane = t & 31;
    const int g    = lane >> 2;
    const int c4   = lane & 3;
    const int m0   = blockIdx.y * (64 * SETS);
    const int e0   = blockIdx.x * 64;

    const float* A;
    const float* Wt;
    if (KIND == 0) {
        A = A_in;
        if (e0 < 256)      Wt = Wq  + (size_t)e0 * KK;
        else if (e0 < 768) Wt = Wkv + (size_t)(e0 - 256) * KK;
        else               Wt = Wg  + (size_t)(e0 - 768) * KK;
    } else {
        A = (const float*)g_t;
        Wt = Wq + (size_t)e0 * KK;   // Wq slot carries Wo for KIND 1
    }

    float s[SETS][8][4];
#pragma unroll
    for (int st = 0; st < SETS; st++)
#pragma unroll
        for (int nt = 0; nt < 8; nt++)
            s[st][nt][0] = s[st][nt][1] = s[st][nt][2] = s[st][nt][3] = 0.f;

    const int row0 = warp * (16 * SETS) + g;

    for (int k0 = 0; k0 < KK; k0 += 32) {
        __syncthreads();
#pragma unroll
        for (int l = 0; l < 4 * SETS; l++) {
            int idx = t + (l << 7);
            int r   = idx >> 3;
            int c   = (idx & 7) << 2;
            float4 a4 = *(const float4*)(A + (size_t)(m0 + r) * KK + k0 + c);
            float4 ac;
            ac.x = __uint_as_float(f2tf32(a4.x));
            ac.y = __uint_as_float(f2tf32(a4.y));
            ac.z = __uint_as_float(f2tf32(a4.z));
            ac.w = __uint_as_float(f2tf32(a4.w));
            *(float4*)&As[r * PSTRIDE + c] = ac;
        }
#pragma unroll
        for (int l = 0; l < 4; l++) {
            int idx = t + (l << 7);
            int r   = idx >> 3;
            int c   = (idx & 7) << 2;
            float4 w4 = *(const float4*)(Wt + (size_t)r * KK + k0 + c);
            float4 wc;
            wc.x = __uint_as_float(f2tf32(w4.x));
            wc.y = __uint_as_float(f2tf32(w4.y));
            wc.z = __uint_as_float(f2tf32(w4.z));
            wc.w = __uint_as_float(f2tf32(w4.w));
            *(float4*)&Bs[r * PSTRIDE + c] = wc;
        }
        __syncthreads();

#pragma unroll
        for (int kk = 0; kk < 4; kk++) {
            uint32_t a[SETS][4];
#pragma unroll
            for (int st = 0; st < SETS; st++) {
                int rr = row0 + st * 16;
                a[st][0] = __float_as_uint(As[rr * PSTRIDE + kk * 8 + c4]);
                a[st][1] = __float_as_uint(As[(rr + 8) * PSTRIDE + kk * 8 + c4]);
                a[st][2] = __float_as_uint(As[rr * PSTRIDE + kk * 8 + c4 + 4]);
                a[st][3] = __float_as_uint(As[(rr + 8) * PSTRIDE + kk * 8 + c4 + 4]);
            }
#pragma unroll
            for (int nt = 0; nt < 8; nt++) {
                uint32_t b0 = __float_as_uint(Bs[(nt * 8 + g) * PSTRIDE + kk * 8 + c4]);
                uint32_t b1 = __float_as_uint(Bs[(nt * 8 + g) * PSTRIDE + kk * 8 + c4 + 4]);
#pragma unroll
                for (int st = 0; st < SETS; st++)
                    mma_tf32(s[st][nt], a[st], b0, b1);
            }
        }
    }

#pragma unroll
    for (int st = 0; st < SETS; st++) {
#pragma unroll
        for (int half = 0; half < 2; half++) {
            int m = m0 + row0 + st * 16 + half * 8;
            int b = m >> 10;
            int n = m & 1023;
#pragma unroll
            for (int nt = 0; nt < 8; nt++) {
                int e = e0 + nt * 8 + (c4 << 1);
                float v0 = half ? s[st][nt][2] : s[st][nt][0];
                float v1 = half ? s[st][nt][3] : s[st][nt][1];
                if (KIND == 1) {
                    float2 r;
                    r.x = v0 + bo[e];
                    r.y = v1 + bo[e + 1];
                    *(float2*)(out + (size_t)m * DQ + e) = r;
                } else if (e0 < 256) {
                    int h = e >> 5, d = e & 31;
                    float2 r; r.x = v0 * QSCALE; r.y = v1 * QSCALE;
                    *(float2*)(g_q + (((size_t)(b * HH + h) * NN + n) << 5) + d) = r;
                } else if (e0 < 512) {
                    int e2 = e - 256;
                    int h = e2 >> 5, d = e2 & 31;
                    float2 r; r.x = v0; r.y = v1;
                    *(float2*)(g_k + (((size_t)(b * HH + h) * NN + n) << 5) + d) = r;
                } else if (e0 < 768) {
                    int e2 = e - 512;
                    int h = e2 >> 5, d = e2 & 31;
                    float2 r; r.x = v0; r.y = v1;
                    *(float2*)(g_v + (((size_t)(b * HH + h) * NN + n) << 5) + d) = r;
                } else {
                    int e2 = e - 768;
                    float z0 = v0 + bg[e2];
                    float z1 = v1 + bg[e2 + 1];
                    float2 r;
                    r.x = 1.f / (1.f + __expf(-z0));
                    r.y = 1.f / (1.f + __expf(-z1));
                    *(float2*)(g_gate + (size_t)m * DQ + e2) = r;
                }
            }
        }
    }
}

// ---------------- attention via mma.sync tf32, 2 row-sets per warp ----------------
// Block = 128 threads (4 warps), 128 query rows of one (b,h); grid (8, 32).
// Warp owns 32 rows: sets at +0 and +16. B-fragments shared across sets.
#define K_STRIDE 36
#define V_STRIDE 40

__global__ __launch_bounds__(128, 2) void attn_mma_kernel(
    const float* __restrict__ bias, const float* __restrict__ mask)
{
    __shared__ float Ks[64 * K_STRIDE];
    __shared__ float Vs[64 * V_STRIDE];

    const int t    = threadIdx.x;
    const int warp = t >> 5;
    const int lane = t & 31;
    const int g    = lane >> 2;
    const int c4   = lane & 3;

    const int bh = blockIdx.y;
    const int b  = bh >> 3;
    const int h  = bh & 7;
    const int i0 = blockIdx.x * 128;
    const int row0 = i0 + warp * 32 + g;   // set st: rows row0+st*16, +8

    const float* qbase = g_q + ((size_t)(bh * NN) << 5);
    uint32_t qa[2][4][4];
#pragma unroll
    for (int st = 0; st < 2; st++) {
        int rr = row0 + st * 16;
#pragma unroll
        for (int kk = 0; kk < 4; kk++) {
            qa[st][kk][0] = f2tf32(qbase[((size_t)rr << 5) + kk * 8 + c4]);
            qa[st][kk][1] = f2tf32(qbase[((size_t)(rr + 8) << 5) + kk * 8 + c4]);
            qa[st][kk][2] = f2tf32(qbase[((size_t)rr << 5) + kk * 8 + c4 + 4]);
            qa[st][kk][3] = f2tf32(qbase[((size_t)(rr + 8) << 5) + kk * 8 + c4 + 4]);
        }
    }

    bool rv[2][2];
#pragma unroll
    for (int st = 0; st < 2; st++) {
        rv[st][0] = mask[b * NN + row0 + st * 16] > 0.f;
        rv[st][1] = mask[b * NN + row0 + st * 16 + 8] > 0.f;
    }

    const float* Kg = g_k + ((size_t)bh << 15);
    const float* Vg = g_v + ((size_t)bh << 15);
    const float* biasb = bias + ((size_t)(bh * NN + row0) << 10);
    const float* mrow  = mask + b * NN;

    float mx[2][2], l[2][2];
#pragma unroll
    for (int st = 0; st < 2; st++) {
        mx[st][0] = mx[st][1] = -1e30f;
        l[st][0] = l[st][1] = 0.f;
    }
    float o[2][4][4];
#pragma unroll
    for (int st = 0; st < 2; st++)
#pragma unroll
        for (int nt = 0; nt < 4; nt++)
#pragma unroll
            for (int r = 0; r < 4; r++) o[st][nt][r] = 0.f;

    const int lA = (lane & 28) | (c4 >> 1);
    const int lB = lA | 2;
    const bool odd = (lane & 1);

    for (int j0 = 0; j0 < NN; j0 += 64) {
        __syncthreads();
        // cooperative K/V tile load: 64x32 = 512 float4 each, 4 per thread
#pragma unroll
        for (int q = 0; q < 4; q++) {
            int id = t + (q << 7);
            int r  = id >> 3;
            int dc = (id & 7) << 2;
            float4 kf = *(const float4*)(Kg + ((size_t)(j0 + r) << 5) + dc);
            float4 vf = *(const float4*)(Vg + ((size_t)(j0 + r) << 5) + dc);
            float4 kc, vc;
            kc.x = __uint_as_float(f2tf32(kf.x));
            kc.y = __uint_as_float(f2tf32(kf.y));
            kc.z = __uint_as_float(f2tf32(kf.z));
            kc.w = __uint_as_float(f2tf32(kf.w));
            vc.x = __uint_as_float(f2tf32(vf.x));
            vc.y = __uint_as_float(f2tf32(vf.y));
            vc.z = __uint_as_float(f2tf32(vf.z));
            vc.w = __uint_as_float(f2tf32(vf.w));
            *(float4*)&Ks[r * K_STRIDE + dc] = kc;
            *(float4*)&Vs[r * V_STRIDE + dc] = vc;
        }
        __syncthreads();

        // ---- S = Q K^T : B-fragments shared across both row sets ----
        float s[2][8][4];
#pragma unroll
        for (int st = 0; st < 2; st++)
#pragma unroll
            for (int nt = 0; nt < 8; nt++)
                s[st][nt][0] = s[st][nt][1] = s[st][nt][2] = s[st][nt][3] = 0.f;
#pragma unroll
        for (int nt = 0; nt < 8; nt++) {
#pragma unroll
            for (int kk = 0; kk < 4; kk++) {
                uint32_t b0 = __float_as_uint(Ks[(nt * 8 + g) * K_STRIDE + kk * 8 + c4]);
                uint32_t b1 = __float_as_uint(Ks[(nt * 8 + g) * K_STRIDE + kk * 8 + c4 + 4]);
                mma_tf32(s[0][nt], qa[0][kk], b0, b1);
                mma_tf32(s[1][nt], qa[1][kk], b0, b1);
            }
        }

        // ---- bias + mask (column mask shared across sets) ----
#pragma unroll
        for (int nt = 0; nt < 8; nt++) {
            int jc = j0 + nt * 8 + (c4 << 1);
            float2 mk = *(const float2*)(mrow + jc);
            bool cx = mk.x > 0.f, cy = mk.y > 0.f;
#pragma unroll
            for (int st = 0; st < 2; st++) {
                float2 bz0 = *(const float2*)(biasb + ((size_t)(st * 16) << 10) + jc);
                float2 bz1 = *(const float2*)(biasb + ((size_t)(st * 16 + 8) << 10) + jc);
                s[st][nt][0] = (rv[st][0] && cx) ? s[st][nt][0] + bz0.x : -1e30f;
                s[st][nt][1] = (rv[st][0] && cy) ? s[st][nt][1] + bz0.y : -1e30f;
                s[st][nt][2] = (rv[st][1] && cx) ? s[st][nt][2] + bz1.x : -1e30f;
                s[st][nt][3] = (rv[st][1] && cy) ? s[st][nt][3] + bz1.y : -1e30f;
            }
        }

        // ---- online softmax per set ----
#pragma unroll
        for (int st = 0; st < 2; st++) {
            float tm0 = -1e30f, tm1 = -1e30f;
#pragma unroll
            for (int nt = 0; nt < 8; nt++) {
                tm0 = fmaxf(tm0, fmaxf(s[st][nt][0], s[st][nt][1]));
                tm1 = fmaxf(tm1, fmaxf(s[st][nt][2], s[st][nt][3]));
            }
            tm0 = fmaxf(tm0, __shfl_xor_sync(0xffffffffu, tm0, 1));
            tm0 = fmaxf(tm0, __shfl_xor_sync(0xffffffffu, tm0, 2));
            tm1 = fmaxf(tm1, __shfl_xor_sync(0xffffffffu, tm1, 1));
            tm1 = fmaxf(tm1, __shfl_xor_sync(0xffffffffu, tm1, 2));

            float mn0 = fmaxf(mx[st][0], tm0), mn1 = fmaxf(mx[st][1], tm1);
            float al0 = __expf(mx[st][0] - mn0), al1 = __expf(mx[st][1] - mn1);

            float ps0 = 0.f, ps1 = 0.f;
#pragma unroll
            for (int nt = 0; nt < 8; nt++) {
                s[st][nt][0] = __expf(s[st][nt][0] - mn0);
                s[st][nt][1] = __expf(s[st][nt][1] - mn0);
                s[st][nt][2] = __expf(s[st][nt][2] - mn1);
                s[st][nt][3] = __expf(s[st][nt][3] - mn1);
                ps0 += s[st][nt][0] + s[st][nt][1];
                ps1 += s[st][nt][2] + s[st][nt][3];
            }
            ps0 += __shfl_xor_sync(0xffffffffu, ps0, 1);
            ps0 += __shfl_xor_sync(0xffffffffu, ps0, 2);
            ps1 += __shfl_xor_sync(0xffffffffu, ps1, 1);
            ps1 += __shfl_xor_sync(0xffffffffu, ps1, 2);
            l[st][0] = l[st][0] * al0 + ps0;
            l[st][1] = l[st][1] * al1 + ps1;
            mx[st][0] = mn0; mx[st][1] = mn1;

#pragma unroll
            for (int nt = 0; nt < 4; nt++) {
                o[st][nt][0] *= al0; o[st][nt][1] *= al0;
                o[st][nt][2] *= al1; o[st][nt][3] *= al1;
            }

#pragma unroll
            for (int nt = 0; nt < 8; nt++) {
                s[st][nt][0] = __uint_as_float(f2tf32(s[st][nt][0]));
                s[st][nt][1] = __uint_as_float(f2tf32(s[st][nt][1]));
                s[st][nt][2] = __uint_as_float(f2tf32(s[st][nt][2]));
                s[st][nt][3] = __uint_as_float(f2tf32(s[st][nt][3]));
            }
        }

        // ---- O += P V  (V B-fragments shared across sets) ----
#pragma unroll
        for (int kk = 0; kk < 8; kk++) {
            uint32_t a[2][4];
#pragma unroll
            for (int st = 0; st < 2; st++) {
#pragma unroll
                for (int hv = 0; hv < 2; hv++) {
                    int src = hv ? lB : lA;
                    float w0 = __shfl_sync(0xffffffffu, s[st][kk][0], src);
                    float w1 = __shfl_sync(0xffffffffu, s[st][kk][1], src);
                    float w2 = __shfl_sync(0xffffffffu, s[st][kk][2], src);
                    float w3 = __shfl_sync(0xffffffffu, s[st][kk][3], src);
                    a[st][hv * 2 + 0] = __float_as_uint(odd ? w1 : w0);
                    a[st][hv * 2 + 1] = __float_as_uint(odd ? w3 : w2);
                }
            }
#pragma unroll
            for (int nt = 0; nt < 4; nt++) {
                uint32_t b0 = __float_as_uint(Vs[(kk * 8 + c4) * V_STRIDE + nt * 8 + g]);
                uint32_t b1 = __float_as_uint(Vs[(kk * 8 + c4 + 4) * V_STRIDE + nt * 8 + g]);
                mma_tf32(o[0][nt], a[0], b0, b1);
                mma_tf32(o[1][nt], a[1], b0, b1);
            }
        }
    }

    // ---- epilogue ----
#pragma unroll
    for (int st = 0; st < 2; st++) {
        float inv0 = 1.f / l[st][0], inv1 = 1.f / l[st][1];
        size_t mr0 = (size_t)(b * NN + row0 + st * 16) * DQ + h * 32;
        size_t mr1 = mr0 + (size_t)8 * DQ;
#pragma unroll
        for (int nt = 0; nt < 4; nt++) {
            int dc = nt * 8 + (c4 << 1);
            float2 gt0 = *(const float2*)(g_gate + mr0 + dc);
            float2 gt1 = *(const float2*)(g_gate + mr1 + dc);
            float2 r0, r1;
            r0.x = o[st][nt][0] * inv0 * gt0.x;
            r0.y = o[st][nt][1] * inv0 * gt0.y;
            r1.x = o[st][nt][2] * inv1 * gt1.x;
            r1.y = o[st][nt][3] * inv1 * gt1.y;
            *(float2*)(g_t + mr0 + dc) = r0;
            *(float2*)(g_t + mr1 + dc) = r1;
        }
    }
}

extern "C" void kernel_launch(void* const* d_in, const int* in_sizes, int n_in,
                              void* d_out, int out_size)
{
    const float* x    = (const float*)d_in[0];
    const float* mask = (const float*)d_in[1];
    const float* bias = (const float*)d_in[2];
    const float* Wq   = (const float*)d_in[3];
    const float* Wkv  = (const float*)d_in[4];
    const float* Wo   = (const float*)d_in[5];
    const float* bo   = (const float*)d_in[6];
    const float* Wg   = (const float*)d_in[7];
    const float* bg   = (const float*)d_in[8];
    float* out = (float*)d_out;

    dim3 blk(128);
    // Fused Q + KV + Gate projections (virtual E = 1024), m-tile 128
    proj_kernel<0, 2><<<dim3(16, 32), blk>>>(x, Wq, Wkv, Wg, bg, nullptr, nullptr);
    // Attention (+ gating): 128 rows per block, 2 row-sets per warp
    attn_mma_kernel<<<dim3(NN / 128, BB * HH), blk>>>(bias, mask);
    // Output projection (A = g_t, W = Wo in the Wq slot), m-tile 64
    proj_kernel<1, 1><<<dim3(4, 64), blk>>>(nullptr, Wo, nullptr, nullptr, nullptr, bo, out);
}